// round 1
// baseline (speedup 1.0000x reference)
#include <cuda_runtime.h>
#include <cuda_bf16.h>
#include <math_constants.h>

// Problem constants
#define PB 64
#define PL 196
#define PD 2048
#define PI 512
#define PM (PB * PL)   // 12544

// Scratch (no cudaMalloc allowed)
__device__ float g_T[(size_t)PM * PI];   // fv@W_f + b_f + hs   [12544, 512]
__device__ float g_hs[PB * PI];          // hidden@W_h + b_h    [64, 512]

// ---------------------------------------------------------------------------
// Kernel 1: hs = hidden @ W_h + b_h      [64,512] x [512,512]
// ---------------------------------------------------------------------------
__global__ __launch_bounds__(512) void hs_kernel(const float* __restrict__ hidden,
                                                 const float* __restrict__ Wh,
                                                 const float* __restrict__ bh) {
    __shared__ float h[PI];
    int b = blockIdx.x;
    int i = threadIdx.x;
    h[i] = hidden[b * PI + i];
    __syncthreads();
    float s = bh[i];
#pragma unroll 8
    for (int k = 0; k < PI; k++) {
        s = fmaf(h[k], Wh[k * PI + i], s);
    }
    g_hs[b * PI + i] = s;
}

// ---------------------------------------------------------------------------
// Kernel 2: T = fv @ W_f + b_f + hs[b]   M=12544, N=512, K=2048
// 128x128 block tile, BK=16, 256 threads, 8x8 per thread, register prefetch.
// ---------------------------------------------------------------------------
#define G1_BM 128
#define G1_BN 128
#define G1_BK 16
#define G1_AS 132   // padded stride for As

__global__ __launch_bounds__(256) void gemm1_kernel(const float* __restrict__ A,   // fv [12544,2048]
                                                    const float* __restrict__ W,   // W_f [2048,512]
                                                    const float* __restrict__ bf,  // [512]
                                                    const float* __restrict__ hs)  // g_hs [64,512]
{
    __shared__ float As[G1_BK][G1_AS];
    __shared__ float Bs[G1_BK][G1_BN];

    const int tid = threadIdx.x;
    const int tx = tid & 15;         // 0..15 -> cols
    const int ty = tid >> 4;         // 0..15 -> rows
    const int rowBase = blockIdx.y * G1_BM;
    const int colBase = blockIdx.x * G1_BN;

    float acc[8][8];
#pragma unroll
    for (int i = 0; i < 8; i++)
#pragma unroll
        for (int j = 0; j < 8; j++) acc[i][j] = 0.0f;

    float4 pa[2], pb[2];

    // indices for loads (512 float4 each tile, 2 per thread)
    const int af0 = tid, af1 = tid + 256;
    const int ar0 = af0 >> 2, aa0 = af0 & 3;
    const int ar1 = af1 >> 2, aa1 = af1 & 3;
    const int br0 = af0 >> 5, bb0 = af0 & 31;
    const int br1 = af1 >> 5, bb1 = af1 & 31;

    const float* Arow0 = A + (size_t)(rowBase + ar0) * PD;
    const float* Arow1 = A + (size_t)(rowBase + ar1) * PD;

    // load tile 0
    pa[0] = *(const float4*)(Arow0 + aa0 * 4);
    pa[1] = *(const float4*)(Arow1 + aa1 * 4);
    pb[0] = *(const float4*)(W + (size_t)br0 * PI + colBase + bb0 * 4);
    pb[1] = *(const float4*)(W + (size_t)br1 * PI + colBase + bb1 * 4);

    // store tile 0
    {
        const float* p = (const float*)&pa[0];
        As[aa0 * 4 + 0][ar0] = p[0]; As[aa0 * 4 + 1][ar0] = p[1];
        As[aa0 * 4 + 2][ar0] = p[2]; As[aa0 * 4 + 3][ar0] = p[3];
        p = (const float*)&pa[1];
        As[aa1 * 4 + 0][ar1] = p[0]; As[aa1 * 4 + 1][ar1] = p[1];
        As[aa1 * 4 + 2][ar1] = p[2]; As[aa1 * 4 + 3][ar1] = p[3];
        *(float4*)&Bs[br0][bb0 * 4] = pb[0];
        *(float4*)&Bs[br1][bb1 * 4] = pb[1];
    }
    __syncthreads();

    const int NKT = PD / G1_BK;   // 128
    for (int kt = 1; kt < NKT; kt++) {
        const int k0 = kt * G1_BK;
        // prefetch next tile into registers
        pa[0] = *(const float4*)(Arow0 + k0 + aa0 * 4);
        pa[1] = *(const float4*)(Arow1 + k0 + aa1 * 4);
        pb[0] = *(const float4*)(W + (size_t)(k0 + br0) * PI + colBase + bb0 * 4);
        pb[1] = *(const float4*)(W + (size_t)(k0 + br1) * PI + colBase + bb1 * 4);

        // compute on current smem tile
#pragma unroll
        for (int k = 0; k < G1_BK; k++) {
            float a[8], bb[8];
            *(float4*)&a[0] = *(float4*)&As[k][ty * 8];
            *(float4*)&a[4] = *(float4*)&As[k][ty * 8 + 4];
            *(float4*)&bb[0] = *(float4*)&Bs[k][tx * 8];
            *(float4*)&bb[4] = *(float4*)&Bs[k][tx * 8 + 4];
#pragma unroll
            for (int i = 0; i < 8; i++)
#pragma unroll
                for (int j = 0; j < 8; j++) acc[i][j] = fmaf(a[i], bb[j], acc[i][j]);
        }
        __syncthreads();
        // store prefetched tile
        {
            const float* p = (const float*)&pa[0];
            As[aa0 * 4 + 0][ar0] = p[0]; As[aa0 * 4 + 1][ar0] = p[1];
            As[aa0 * 4 + 2][ar0] = p[2]; As[aa0 * 4 + 3][ar0] = p[3];
            p = (const float*)&pa[1];
            As[aa1 * 4 + 0][ar1] = p[0]; As[aa1 * 4 + 1][ar1] = p[1];
            As[aa1 * 4 + 2][ar1] = p[2]; As[aa1 * 4 + 3][ar1] = p[3];
            *(float4*)&Bs[br0][bb0 * 4] = pb[0];
            *(float4*)&Bs[br1][bb1 * 4] = pb[1];
        }
        __syncthreads();
    }
    // last tile compute
#pragma unroll
    for (int k = 0; k < G1_BK; k++) {
        float a[8], bb[8];
        *(float4*)&a[0] = *(float4*)&As[k][ty * 8];
        *(float4*)&a[4] = *(float4*)&As[k][ty * 8 + 4];
        *(float4*)&bb[0] = *(float4*)&Bs[k][tx * 8];
        *(float4*)&bb[4] = *(float4*)&Bs[k][tx * 8 + 4];
#pragma unroll
        for (int i = 0; i < 8; i++)
#pragma unroll
            for (int j = 0; j < 8; j++) acc[i][j] = fmaf(a[i], bb[j], acc[i][j]);
    }

    // epilogue: + b_f + hs[b], store to g_T
    const int col = colBase + tx * 8;
    float4 bf0 = *(const float4*)(bf + col);
    float4 bf1 = *(const float4*)(bf + col + 4);
#pragma unroll
    for (int i = 0; i < 8; i++) {
        int row = rowBase + ty * 8 + i;
        int b = row / PL;
        float4 h0 = *(const float4*)(hs + b * PI + col);
        float4 h1 = *(const float4*)(hs + b * PI + col + 4);
        float4 o0, o1;
        o0.x = acc[i][0] + bf0.x + h0.x;
        o0.y = acc[i][1] + bf0.y + h0.y;
        o0.z = acc[i][2] + bf0.z + h0.z;
        o0.w = acc[i][3] + bf0.w + h0.w;
        o1.x = acc[i][4] + bf1.x + h1.x;
        o1.y = acc[i][5] + bf1.y + h1.y;
        o1.z = acc[i][6] + bf1.z + h1.z;
        o1.w = acc[i][7] + bf1.w + h1.w;
        *(float4*)(g_T + (size_t)row * PI + col) = o0;
        *(float4*)(g_T + (size_t)row * PI + col + 4) = o1;
    }
}

// ---------------------------------------------------------------------------
// Kernel 3 (fused): per (b, 64-wide d-chunk)
//   e[l, d] = T[b,l,:] @ W_a[:, d] + b_a[d]        (all 196 l-rows in-block)
//   alpha = softmax over l  (intra-block)
//   z[b,d] = sum_l alpha * fv
// 224 threads = 28 row-groups x 8 col-groups, 7x8 per thread.
// ---------------------------------------------------------------------------
#define F_BN 64
#define F_BK 32
#define F_TS 33     // padded Ts row stride

__global__ __launch_bounds__(224) void fused2_kernel(const float* __restrict__ Wa,  // [512,2048]
                                                     const float* __restrict__ ba,  // [2048]
                                                     const float* __restrict__ fv,  // [64,196,2048]
                                                     float* __restrict__ z,         // [64,2048]
                                                     float* __restrict__ alpha)     // [64,196,2048]
{
    __shared__ float Ts[PL * F_TS];        // 196 x 33
    __shared__ float Was[F_BK * F_BN];     // 32 x 64
    __shared__ float red[28 * F_BN];       // 28 x 64
    __shared__ float colmax[F_BN];
    __shared__ float colsum[F_BN];

    const int tid = threadIdx.x;
    const int tc = tid & 7;     // 0..7  -> 8 cols each
    const int tr = tid >> 3;    // 0..27 -> 7 rows each
    const int b = blockIdx.y;
    const int dbase = blockIdx.x * F_BN;

    float acc[7][8];
#pragma unroll
    for (int r = 0; r < 7; r++)
#pragma unroll
        for (int j = 0; j < 8; j++) acc[r][j] = 0.0f;

    const float* Tb = g_T + (size_t)b * PL * PI;

    for (int kt = 0; kt < PI / F_BK; kt++) {   // 16 chunks
        const int k0 = kt * F_BK;
        // load T tile: 196 x 32 = 1568 float4 / 224 threads = 7 each
#pragma unroll
        for (int i = 0; i < 7; i++) {
            int f = tid + i * 224;
            int l = f >> 3;
            int k4 = f & 7;
            float4 v = *(const float4*)(Tb + (size_t)l * PI + k0 + k4 * 4);
            float* dst = &Ts[l * F_TS + k4 * 4];
            dst[0] = v.x; dst[1] = v.y; dst[2] = v.z; dst[3] = v.w;
        }
        // load Wa tile: 32 x 64 = 512 float4
#pragma unroll
        for (int i = 0; i < 3; i++) {
            int f = tid + i * 224;
            if (f < 512) {
                int kr = f >> 4;
                int c4 = f & 15;
                *(float4*)&Was[kr * F_BN + c4 * 4] =
                    *(const float4*)(Wa + (size_t)(k0 + kr) * PD + dbase + c4 * 4);
            }
        }
        __syncthreads();
#pragma unroll
        for (int kk = 0; kk < F_BK; kk++) {
            float t[7];
#pragma unroll
            for (int r = 0; r < 7; r++) t[r] = Ts[(tr * 7 + r) * F_TS + kk];
            float w[8];
            *(float4*)&w[0] = *(float4*)&Was[kk * F_BN + tc * 8];
            *(float4*)&w[4] = *(float4*)&Was[kk * F_BN + tc * 8 + 4];
#pragma unroll
            for (int r = 0; r < 7; r++)
#pragma unroll
                for (int j = 0; j < 8; j++) acc[r][j] = fmaf(t[r], w[j], acc[r][j]);
        }
        __syncthreads();
    }

    // + b_a
    float bias[8];
    *(float4*)&bias[0] = *(const float4*)(ba + dbase + tc * 8);
    *(float4*)&bias[4] = *(const float4*)(ba + dbase + tc * 8 + 4);
#pragma unroll
    for (int r = 0; r < 7; r++)
#pragma unroll
        for (int j = 0; j < 8; j++) acc[r][j] += bias[j];

    // ---- softmax over l (196 rows, spread across 28 row-groups) ----
    // column max
    float lm[8];
#pragma unroll
    for (int j = 0; j < 8; j++) {
        float m = acc[0][j];
#pragma unroll
        for (int r = 1; r < 7; r++) m = fmaxf(m, acc[r][j]);
        lm[j] = m;
    }
#pragma unroll
    for (int j = 0; j < 8; j++) red[tr * F_BN + tc * 8 + j] = lm[j];
    __syncthreads();
    if (tid < F_BN) {
        float m = -CUDART_INF_F;
#pragma unroll
        for (int t = 0; t < 28; t++) m = fmaxf(m, red[t * F_BN + tid]);
        colmax[tid] = m;
    }
    __syncthreads();

    float cm[8];
#pragma unroll
    for (int j = 0; j < 8; j++) cm[j] = colmax[tc * 8 + j];

    // exp + column sum
    float ls[8];
#pragma unroll
    for (int j = 0; j < 8; j++) ls[j] = 0.0f;
#pragma unroll
    for (int r = 0; r < 7; r++)
#pragma unroll
        for (int j = 0; j < 8; j++) {
            float e = __expf(acc[r][j] - cm[j]);
            acc[r][j] = e;
            ls[j] += e;
        }
#pragma unroll
    for (int j = 0; j < 8; j++) red[tr * F_BN + tc * 8 + j] = ls[j];
    __syncthreads();
    if (tid < F_BN) {
        float s = 0.0f;
#pragma unroll
        for (int t = 0; t < 28; t++) s += red[t * F_BN + tid];
        colsum[tid] = s;
    }
    __syncthreads();

    float inv[8];
#pragma unroll
    for (int j = 0; j < 8; j++) inv[j] = 1.0f / colsum[tc * 8 + j];

    // alpha write + z partial
    float zp[8];
#pragma unroll
    for (int j = 0; j < 8; j++) zp[j] = 0.0f;
#pragma unroll
    for (int r = 0; r < 7; r++) {
        int l = tr * 7 + r;
        size_t base = ((size_t)b * PL + l) * PD + dbase + tc * 8;
        float4 f0 = *(const float4*)(fv + base);
        float4 f1 = *(const float4*)(fv + base + 4);
        float a0 = acc[r][0] * inv[0], a1 = acc[r][1] * inv[1];
        float a2 = acc[r][2] * inv[2], a3 = acc[r][3] * inv[3];
        float a4 = acc[r][4] * inv[4], a5 = acc[r][5] * inv[5];
        float a6 = acc[r][6] * inv[6], a7 = acc[r][7] * inv[7];
        float4 o0 = {a0, a1, a2, a3};
        float4 o1 = {a4, a5, a6, a7};
        *(float4*)(alpha + base) = o0;
        *(float4*)(alpha + base + 4) = o1;
        zp[0] = fmaf(a0, f0.x, zp[0]); zp[1] = fmaf(a1, f0.y, zp[1]);
        zp[2] = fmaf(a2, f0.z, zp[2]); zp[3] = fmaf(a3, f0.w, zp[3]);
        zp[4] = fmaf(a4, f1.x, zp[4]); zp[5] = fmaf(a5, f1.y, zp[5]);
        zp[6] = fmaf(a6, f1.z, zp[6]); zp[7] = fmaf(a7, f1.w, zp[7]);
    }
    // reduce z over row-groups
#pragma unroll
    for (int j = 0; j < 8; j++) red[tr * F_BN + tc * 8 + j] = zp[j];
    __syncthreads();
    if (tid < F_BN) {
        float s = 0.0f;
#pragma unroll
        for (int t = 0; t < 28; t++) s += red[t * F_BN + tid];
        z[b * PD + dbase + tid] = s;
    }
}

// ---------------------------------------------------------------------------
// Launch
// ---------------------------------------------------------------------------
extern "C" void kernel_launch(void* const* d_in, const int* in_sizes, int n_in,
                              void* d_out, int out_size) {
    const float* fv     = (const float*)d_in[0];
    const float* hidden = (const float*)d_in[1];
    const float* W_f    = (const float*)d_in[2];
    const float* b_f    = (const float*)d_in[3];
    const float* W_h    = (const float*)d_in[4];
    const float* b_h    = (const float*)d_in[5];
    const float* W_a    = (const float*)d_in[6];
    const float* b_a    = (const float*)d_in[7];

    float* out   = (float*)d_out;
    float* z     = out;                 // [64, 2048]
    float* alpha = out + (size_t)PB * PD;  // [64, 196, 2048]

    float* hs_ptr;
    cudaGetSymbolAddress((void**)&hs_ptr, g_hs);

    hs_kernel<<<PB, PI>>>(hidden, W_h, b_h);

    dim3 g1(PI / G1_BN, PM / G1_BM);    // (4, 98)
    gemm1_kernel<<<g1, 256>>>(fv, W_f, b_f, hs_ptr);

    dim3 g2(PD / F_BN, PB);             // (32, 64)
    fused2_kernel<<<g2, 224>>>(W_a, b_a, fv, z, alpha);
}

// round 12
// speedup vs baseline: 2.0399x; 2.0399x over previous
#include <cuda_runtime.h>
#include <cuda_bf16.h>
#include <cstdint>
#include <math_constants.h>

// Problem constants
#define PB 64
#define PL 196
#define PD 2048
#define PI 512
#define PM (PB * PL)   // 12544

// ---------------------------------------------------------------------------
// Scratch (__device__ globals; no cudaMalloc allowed)
// ---------------------------------------------------------------------------
__device__ __align__(1024) __nv_bfloat16 g_fv_hi[(size_t)PM * PD];
__device__ __align__(1024) __nv_bfloat16 g_fv_lo[(size_t)PM * PD];
__device__ __align__(1024) __nv_bfloat16 g_Wft_hi[(size_t)PI * PD];  // W_f^T [512,2048]
__device__ __align__(1024) __nv_bfloat16 g_Wft_lo[(size_t)PI * PD];
__device__ __align__(1024) __nv_bfloat16 g_Wat_hi[(size_t)PD * PI];  // W_a^T [2048,512]
__device__ __align__(1024) __nv_bfloat16 g_Wat_lo[(size_t)PD * PI];
__device__ __align__(1024) __nv_bfloat16 g_T_hi[(size_t)PM * PI];
__device__ __align__(1024) __nv_bfloat16 g_T_lo[(size_t)PM * PI];
__device__ __align__(1024) float g_hs[PB * PI];
__device__ __align__(1024) float g_E[(size_t)PM * PD];

// ---------------------------------------------------------------------------
// Helpers (baseline ISA only: cp.async + mma.sync, both sm_80+)
// ---------------------------------------------------------------------------
__device__ __forceinline__ uint32_t smem_u32(const void* p) {
    uint32_t a;
    asm("{ .reg .u64 t; cvta.to.shared.u64 t, %1; cvt.u32.u64 %0, t; }" : "=r"(a) : "l"(p));
    return a;
}

#define CP_ASYNC16(dst, src) \
    asm volatile("cp.async.cg.shared.global [%0], [%1], 16;" :: "r"(dst), "l"(src))
#define CP_ASYNC_COMMIT() asm volatile("cp.async.commit_group;" ::: "memory")
#define CP_ASYNC_WAIT1() asm volatile("cp.async.wait_group 1;" ::: "memory")

__device__ __forceinline__ void mma_bf16(float* c, const uint32_t* a, const uint32_t* b) {
    asm volatile(
        "mma.sync.aligned.m16n8k16.row.col.f32.bf16.bf16.f32 "
        "{%0,%1,%2,%3}, {%4,%5,%6,%7}, {%8,%9}, {%0,%1,%2,%3};"
        : "+f"(c[0]), "+f"(c[1]), "+f"(c[2]), "+f"(c[3])
        : "r"(a[0]), "r"(a[1]), "r"(a[2]), "r"(a[3]), "r"(b[0]), "r"(b[1]));
}

__device__ __forceinline__ void split2(float v, __nv_bfloat16& h, __nv_bfloat16& l) {
    h = __float2bfloat16(v);
    l = __float2bfloat16(v - __bfloat162float(h));
}

// ---------------------------------------------------------------------------
// Kernel: split fv -> bf16 hi/lo
// ---------------------------------------------------------------------------
__global__ __launch_bounds__(256) void split_fv_kernel(const float* __restrict__ in) {
    size_t i = (size_t)blockIdx.x * blockDim.x + threadIdx.x;   // float4 index
    const size_t n4 = (size_t)PM * PD / 4;
    if (i >= n4) return;
    float4 v = ((const float4*)in)[i];
    __nv_bfloat16 h0, h1, h2, h3, l0, l1, l2, l3;
    split2(v.x, h0, l0); split2(v.y, h1, l1);
    split2(v.z, h2, l2); split2(v.w, h3, l3);
    __nv_bfloat162* ph = (__nv_bfloat162*)g_fv_hi;
    __nv_bfloat162* pl = (__nv_bfloat162*)g_fv_lo;
    ph[2 * i]     = __nv_bfloat162(h0, h1);
    ph[2 * i + 1] = __nv_bfloat162(h2, h3);
    pl[2 * i]     = __nv_bfloat162(l0, l1);
    pl[2 * i + 1] = __nv_bfloat162(l2, l3);
}

// ---------------------------------------------------------------------------
// Kernel: transpose [R?,C] -> [C,R], split to bf16 hi/lo  (out stride = R)
// ---------------------------------------------------------------------------
__global__ void tsplit_kernel(const float* __restrict__ in,
                              __nv_bfloat16* __restrict__ hi,
                              __nv_bfloat16* __restrict__ lo,
                              int R, int C) {
    __shared__ float tile[32][33];
    int r0 = blockIdx.y * 32, c0 = blockIdx.x * 32;
    int tx = threadIdx.x, ty = threadIdx.y;   // (32, 8)
#pragma unroll
    for (int j = 0; j < 32; j += 8)
        tile[ty + j][tx] = in[(size_t)(r0 + ty + j) * C + c0 + tx];
    __syncthreads();
#pragma unroll
    for (int j = 0; j < 32; j += 8) {
        float v = tile[tx][ty + j];
        __nv_bfloat16 h, l;
        split2(v, h, l);
        size_t o = (size_t)(c0 + ty + j) * R + r0 + tx;
        hi[o] = h; lo[o] = l;
    }
}

// ---------------------------------------------------------------------------
// Kernel: hs = hidden @ W_h + b_h
// ---------------------------------------------------------------------------
__global__ __launch_bounds__(512) void hs_kernel(const float* __restrict__ hidden,
                                                 const float* __restrict__ Wh,
                                                 const float* __restrict__ bh) {
    __shared__ float h[PI];
    int b = blockIdx.x;
    int i = threadIdx.x;
    h[i] = hidden[b * PI + i];
    __syncthreads();
    float s = bh[i];
#pragma unroll 8
    for (int k = 0; k < PI; k++) s = fmaf(h[k], Wh[k * PI + i], s);
    g_hs[b * PI + i] = s;
}

// ---------------------------------------------------------------------------
// mma.sync GEMM (bf16 3-MMA hi/lo split):  D[m,n] = sum_k A[m,k]*B[n,k]
// BM=BN=128, BK=32, 3-stage cp.async ring, 256 threads (8 warps, m64 x n32 each)
// EPI1: out = D + b_f + hs[b]  -> split to g_T_hi/lo (bf16)
// else: out = D + b_a          -> g_E (fp32)
// ---------------------------------------------------------------------------
#define GK_BM 128
#define GK_BN 128
#define GK_BK 32
#define GK_RS 40                         // padded row stride (bf16 elements)
#define GK_TILE_B (GK_BM * GK_RS * 2)    // 10240 bytes
#define GK_STAGE_B (4 * GK_TILE_B)       // Ah, Al, Bh, Bl  = 40960
#define GK_STAGES 3
#define GEMM_SMEM (GK_STAGES * GK_STAGE_B)  // 122880

template<int NK, bool EPI1>
__global__ __launch_bounds__(256) void gemm_kernel(const float* __restrict__ bias) {
    constexpr int K = NK * GK_BK;
    extern __shared__ char smem[];
    const uint32_t sbase = smem_u32(smem);

    const int tid = threadIdx.x;
    const int wid = tid >> 5;
    const int lane = tid & 31;
    const int tq = lane >> 2;    // 0..7
    const int tp = lane & 3;     // 0..3
    const int warp_m = wid & 1;  // 2
    const int warp_n = wid >> 1; // 4
    const int m0 = warp_m * 64;
    const int n0 = warp_n * 32;

    const __nv_bfloat16* Agh = EPI1 ? g_fv_hi : g_T_hi;
    const __nv_bfloat16* Agl = EPI1 ? g_fv_lo : g_T_lo;
    const __nv_bfloat16* Bgh = EPI1 ? g_Wft_hi : g_Wat_hi;
    const __nv_bfloat16* Bgl = EPI1 ? g_Wft_lo : g_Wat_lo;

    const int rowBase = blockIdx.y * GK_BM;
    const int colBase = blockIdx.x * GK_BN;
    const __nv_bfloat16* A0h = Agh + (size_t)rowBase * K;
    const __nv_bfloat16* A0l = Agl + (size_t)rowBase * K;
    const __nv_bfloat16* B0h = Bgh + (size_t)colBase * K;
    const __nv_bfloat16* B0l = Bgl + (size_t)colBase * K;

    float acc[4][4][4];
#pragma unroll
    for (int mi = 0; mi < 4; mi++)
#pragma unroll
        for (int ni = 0; ni < 4; ni++)
#pragma unroll
            for (int e = 0; e < 4; e++) acc[mi][ni][e] = 0.0f;

    // load slots: 512 16B-chunks per tile (128 rows x 4), 2 per thread
    const int s0 = tid, s1 = tid + 256;
    const int r0_ = s0 >> 2, ch0 = s0 & 3;
    const int r1_ = s1 >> 2, ch1 = s1 & 3;
    const uint32_t so0 = (uint32_t)(r0_ * (GK_RS * 2) + ch0 * 16);
    const uint32_t so1 = (uint32_t)(r1_ * (GK_RS * 2) + ch1 * 16);

    auto load_stage = [&](int kt, int stg) {
        const uint32_t sb = sbase + stg * GK_STAGE_B;
        const int k0 = kt * GK_BK;
        {
            const size_t ga = (size_t)r0_ * K + k0 + ch0 * 8;
            CP_ASYNC16(sb + so0,                 A0h + ga);
            CP_ASYNC16(sb + GK_TILE_B + so0,     A0l + ga);
            CP_ASYNC16(sb + 2 * GK_TILE_B + so0, B0h + ga);
            CP_ASYNC16(sb + 3 * GK_TILE_B + so0, B0l + ga);
        }
        {
            const size_t ga = (size_t)r1_ * K + k0 + ch1 * 8;
            CP_ASYNC16(sb + so1,                 A0h + ga);
            CP_ASYNC16(sb + GK_TILE_B + so1,     A0l + ga);
            CP_ASYNC16(sb + 2 * GK_TILE_B + so1, B0h + ga);
            CP_ASYNC16(sb + 3 * GK_TILE_B + so1, B0l + ga);
        }
        CP_ASYNC_COMMIT();
    };

    // prologue: 2 stages in flight
    load_stage(0, 0);
    load_stage(1, 1);

    int stg_idx = 0;   // stage holding chunk kt
    for (int kt = 0; kt < NK; kt++) {
        // ensure chunk kt's group is complete (at most 1 newer group pending)
        CP_ASYNC_WAIT1();
        __syncthreads();

        // kick off load of chunk kt+2 into the free stage (uniform commit count)
        if (kt + 2 < NK) {
            int free_stg = stg_idx + 2;
            if (free_stg >= GK_STAGES) free_stg -= GK_STAGES;
            load_stage(kt + 2, free_stg);
        } else {
            CP_ASYNC_COMMIT();   // empty group keeps wait_group accounting uniform
        }

        const __nv_bfloat16* stg =
            (const __nv_bfloat16*)(smem + (size_t)stg_idx * GK_STAGE_B);
        const __nv_bfloat16* Ah = stg;
        const __nv_bfloat16* Al = stg + GK_TILE_B / 2;   // byte offset GK_TILE_B
        const __nv_bfloat16* Bh = stg + GK_TILE_B;       // byte offset 2*GK_TILE_B
        const __nv_bfloat16* Bl = stg + 3 * GK_TILE_B / 2;

#pragma unroll
        for (int ks = 0; ks < 2; ks++) {
            const int k0 = ks * 16;
            uint32_t ah[4][4], al[4][4], bh[4][2], bl[4][2];
#pragma unroll
            for (int mi = 0; mi < 4; mi++) {
                const int ra = m0 + mi * 16 + tq;
                ah[mi][0] = *(const uint32_t*)(Ah + ra * GK_RS + k0 + tp * 2);
                ah[mi][1] = *(const uint32_t*)(Ah + (ra + 8) * GK_RS + k0 + tp * 2);
                ah[mi][2] = *(const uint32_t*)(Ah + ra * GK_RS + k0 + 8 + tp * 2);
                ah[mi][3] = *(const uint32_t*)(Ah + (ra + 8) * GK_RS + k0 + 8 + tp * 2);
                al[mi][0] = *(const uint32_t*)(Al + ra * GK_RS + k0 + tp * 2);
                al[mi][1] = *(const uint32_t*)(Al + (ra + 8) * GK_RS + k0 + tp * 2);
                al[mi][2] = *(const uint32_t*)(Al + ra * GK_RS + k0 + 8 + tp * 2);
                al[mi][3] = *(const uint32_t*)(Al + (ra + 8) * GK_RS + k0 + 8 + tp * 2);
            }
#pragma unroll
            for (int ni = 0; ni < 4; ni++) {
                const int rb = n0 + ni * 8 + tq;
                bh[ni][0] = *(const uint32_t*)(Bh + rb * GK_RS + k0 + tp * 2);
                bh[ni][1] = *(const uint32_t*)(Bh + rb * GK_RS + k0 + 8 + tp * 2);
                bl[ni][0] = *(const uint32_t*)(Bl + rb * GK_RS + k0 + tp * 2);
                bl[ni][1] = *(const uint32_t*)(Bl + rb * GK_RS + k0 + 8 + tp * 2);
            }
#pragma unroll
            for (int mi = 0; mi < 4; mi++)
#pragma unroll
                for (int ni = 0; ni < 4; ni++) {
                    mma_bf16(acc[mi][ni], ah[mi], bh[ni]);
                    mma_bf16(acc[mi][ni], ah[mi], bl[ni]);
                    mma_bf16(acc[mi][ni], al[mi], bh[ni]);
                }
        }
        __syncthreads();
        if (++stg_idx == GK_STAGES) stg_idx = 0;
    }

    // epilogue: c0,c1 at (row=tq, col=tp*2), c2,c3 at (row=tq+8)
#pragma unroll
    for (int mi = 0; mi < 4; mi++) {
        const int gr0 = rowBase + m0 + mi * 16 + tq;
        const int gr1 = gr0 + 8;
#pragma unroll
        for (int ni = 0; ni < 4; ni++) {
            const int gc = colBase + n0 + ni * 8 + tp * 2;
            float v0 = acc[mi][ni][0], v1 = acc[mi][ni][1];
            float v2 = acc[mi][ni][2], v3 = acc[mi][ni][3];
            const float b0 = bias[gc], b1 = bias[gc + 1];
            if (EPI1) {
                const int bb0 = gr0 / PL;
                const int bb1 = gr1 / PL;
                v0 += b0 + g_hs[bb0 * PI + gc];
                v1 += b1 + g_hs[bb0 * PI + gc + 1];
                v2 += b0 + g_hs[bb1 * PI + gc];
                v3 += b1 + g_hs[bb1 * PI + gc + 1];
                __nv_bfloat16 h0, h1, h2, h3, l0, l1, l2, l3;
                split2(v0, h0, l0); split2(v1, h1, l1);
                split2(v2, h2, l2); split2(v3, h3, l3);
                const size_t o0 = ((size_t)gr0 * PI + gc) >> 1;
                const size_t o1 = ((size_t)gr1 * PI + gc) >> 1;
                ((__nv_bfloat162*)g_T_hi)[o0] = __nv_bfloat162(h0, h1);
                ((__nv_bfloat162*)g_T_lo)[o0] = __nv_bfloat162(l0, l1);
                ((__nv_bfloat162*)g_T_hi)[o1] = __nv_bfloat162(h2, h3);
                ((__nv_bfloat162*)g_T_lo)[o1] = __nv_bfloat162(l2, l3);
            } else {
                float2 w0 = {v0 + b0, v1 + b1};
                float2 w1 = {v2 + b0, v3 + b1};
                *(float2*)(g_E + (size_t)gr0 * PD + gc) = w0;
                *(float2*)(g_E + (size_t)gr1 * PD + gc) = w1;
            }
        }
    }
}

// ---------------------------------------------------------------------------
// Softmax over L + alpha write + z reduce. Block per (b, 64-wide d-chunk).
// 224 threads = 28 row-groups x 8 col-groups; 7x8 elements per thread.
// ---------------------------------------------------------------------------
__global__ __launch_bounds__(224) void softmax_kernel(const float* __restrict__ fv,
                                                      float* __restrict__ z,
                                                      float* __restrict__ alpha) {
    __shared__ float red[28 * 64];
    __shared__ float colmax[64];
    __shared__ float colsum[64];

    const int tid = threadIdx.x;
    const int tc = tid & 7;
    const int tr = tid >> 3;
    const int b = blockIdx.y;
    const int dbase = blockIdx.x * 64;

    float acc[7][8];
#pragma unroll
    for (int r = 0; r < 7; r++) {
        const int l = tr * 7 + r;
        const size_t base = ((size_t)b * PL + l) * PD + dbase + tc * 8;
        float4 e0 = *(const float4*)(g_E + base);
        float4 e1 = *(const float4*)(g_E + base + 4);
        acc[r][0] = e0.x; acc[r][1] = e0.y; acc[r][2] = e0.z; acc[r][3] = e0.w;
        acc[r][4] = e1.x; acc[r][5] = e1.y; acc[r][6] = e1.z; acc[r][7] = e1.w;
    }

    float lm[8];
#pragma unroll
    for (int j = 0; j < 8; j++) {
        float m = acc[0][j];
#pragma unroll
        for (int r = 1; r < 7; r++) m = fmaxf(m, acc[r][j]);
        lm[j] = m;
    }
#pragma unroll
    for (int j = 0; j < 8; j++) red[tr * 64 + tc * 8 + j] = lm[j];
    __syncthreads();
    if (tid < 64) {
        float m = -CUDART_INF_F;
#pragma unroll
        for (int t = 0; t < 28; t++) m = fmaxf(m, red[t * 64 + tid]);
        colmax[tid] = m;
    }
    __syncthreads();
    float cm[8];
#pragma unroll
    for (int j = 0; j < 8; j++) cm[j] = colmax[tc * 8 + j];

    float ls[8];
#pragma unroll
    for (int j = 0; j < 8; j++) ls[j] = 0.0f;
#pragma unroll
    for (int r = 0; r < 7; r++)
#pragma unroll
        for (int j = 0; j < 8; j++) {
            float e = __expf(acc[r][j] - cm[j]);
            acc[r][j] = e;
            ls[j] += e;
        }
#pragma unroll
    for (int j = 0; j < 8; j++) red[tr * 64 + tc * 8 + j] = ls[j];
    __syncthreads();
    if (tid < 64) {
        float s = 0.0f;
#pragma unroll
        for (int t = 0; t < 28; t++) s += red[t * 64 + tid];
        colsum[tid] = s;
    }
    __syncthreads();
    float inv[8];
#pragma unroll
    for (int j = 0; j < 8; j++) inv[j] = 1.0f / colsum[tc * 8 + j];

    float zp[8];
#pragma unroll
    for (int j = 0; j < 8; j++) zp[j] = 0.0f;
#pragma unroll
    for (int r = 0; r < 7; r++) {
        const int l = tr * 7 + r;
        const size_t base = ((size_t)b * PL + l) * PD + dbase + tc * 8;
        float4 f0 = *(const float4*)(fv + base);
        float4 f1 = *(const float4*)(fv + base + 4);
        float a0 = acc[r][0] * inv[0], a1 = acc[r][1] * inv[1];
        float a2 = acc[r][2] * inv[2], a3 = acc[r][3] * inv[3];
        float a4 = acc[r][4] * inv[4], a5 = acc[r][5] * inv[5];
        float a6 = acc[r][6] * inv[6], a7 = acc[r][7] * inv[7];
        float4 o0 = {a0, a1, a2, a3};
        float4 o1 = {a4, a5, a6, a7};
        *(float4*)(alpha + base) = o0;
        *(float4*)(alpha + base + 4) = o1;
        zp[0] = fmaf(a0, f0.x, zp[0]); zp[1] = fmaf(a1, f0.y, zp[1]);
        zp[2] = fmaf(a2, f0.z, zp[2]); zp[3] = fmaf(a3, f0.w, zp[3]);
        zp[4] = fmaf(a4, f1.x, zp[4]); zp[5] = fmaf(a5, f1.y, zp[5]);
        zp[6] = fmaf(a6, f1.z, zp[6]); zp[7] = fmaf(a7, f1.w, zp[7]);
    }
#pragma unroll
    for (int j = 0; j < 8; j++) red[tr * 64 + tc * 8 + j] = zp[j];
    __syncthreads();
    if (tid < 64) {
        float s = 0.0f;
#pragma unroll
        for (int t = 0; t < 28; t++) s += red[t * 64 + tid];
        z[b * PD + dbase + tid] = s;
    }
}

// ---------------------------------------------------------------------------
// Launch
// ---------------------------------------------------------------------------
extern "C" void kernel_launch(void* const* d_in, const int* in_sizes, int n_in,
                              void* d_out, int out_size) {
    const float* fv     = (const float*)d_in[0];
    const float* hidden = (const float*)d_in[1];
    const float* W_f    = (const float*)d_in[2];
    const float* b_f    = (const float*)d_in[3];
    const float* W_h    = (const float*)d_in[4];
    const float* b_h    = (const float*)d_in[5];
    const float* W_a    = (const float*)d_in[6];
    const float* b_a    = (const float*)d_in[7];

    float* out   = (float*)d_out;
    float* z     = out;
    float* alpha = out + (size_t)PB * PD;

    cudaFuncSetAttribute(gemm_kernel<PD / GK_BK, true>,
                         cudaFuncAttributeMaxDynamicSharedMemorySize, GEMM_SMEM);
    cudaFuncSetAttribute(gemm_kernel<PI / GK_BK, false>,
                         cudaFuncAttributeMaxDynamicSharedMemorySize, GEMM_SMEM);

    __nv_bfloat16 *wft_hi, *wft_lo, *wat_hi, *wat_lo;
    cudaGetSymbolAddress((void**)&wft_hi, g_Wft_hi);
    cudaGetSymbolAddress((void**)&wft_lo, g_Wft_lo);
    cudaGetSymbolAddress((void**)&wat_hi, g_Wat_hi);
    cudaGetSymbolAddress((void**)&wat_lo, g_Wat_lo);

    // 1) conversions
    {
        size_t n4 = (size_t)PM * PD / 4;
        int blocks = (int)((n4 + 255) / 256);
        split_fv_kernel<<<blocks, 256>>>(fv);
    }
    tsplit_kernel<<<dim3(PI / 32, PD / 32), dim3(32, 8)>>>(W_f, wft_hi, wft_lo, PD, PI);
    tsplit_kernel<<<dim3(PD / 32, PI / 32), dim3(32, 8)>>>(W_a, wat_hi, wat_lo, PI, PD);

    // 2) hs
    hs_kernel<<<PB, PI>>>(hidden, W_h, b_h);

    // 3) GEMM1: T = fv @ W_f + b_f + hs   (M=12544, N=512, K=2048)
    gemm_kernel<PD / GK_BK, true>
        <<<dim3(PI / GK_BN, PM / GK_BM), 256, GEMM_SMEM>>>(b_f);

    // 4) GEMM2: E = T @ W_a + b_a         (M=12544, N=2048, K=512)
    gemm_kernel<PI / GK_BK, false>
        <<<dim3(PD / GK_BN, PM / GK_BM), 256, GEMM_SMEM>>>(b_a);

    // 5) softmax + alpha + z
    softmax_kernel<<<dim3(PD / 64, PB), 224>>>(fv, z, alpha);
}

// round 13
// speedup vs baseline: 2.1072x; 1.0330x over previous
#include <cuda_runtime.h>
#include <cuda_bf16.h>
#include <cstdint>
#include <math_constants.h>

// Problem constants
#define PB 64
#define PL 196
#define PD 2048
#define PI 512
#define PM (PB * PL)   // 12544

// ---------------------------------------------------------------------------
// Scratch (__device__ globals; no cudaMalloc allowed)
// ---------------------------------------------------------------------------
__device__ __align__(1024) __nv_bfloat16 g_fv_hi[(size_t)PM * PD];
__device__ __align__(1024) __nv_bfloat16 g_fv_lo[(size_t)PM * PD];
__device__ __align__(1024) __nv_bfloat16 g_Wft_hi[(size_t)PI * PD];  // W_f^T [512,2048]
__device__ __align__(1024) __nv_bfloat16 g_Wft_lo[(size_t)PI * PD];
__device__ __align__(1024) __nv_bfloat16 g_Wat_hi[(size_t)PD * PI];  // W_a^T [2048,512]
__device__ __align__(1024) __nv_bfloat16 g_Wat_lo[(size_t)PD * PI];
__device__ __align__(1024) __nv_bfloat16 g_T_hi[(size_t)PM * PI];
__device__ __align__(1024) __nv_bfloat16 g_T_lo[(size_t)PM * PI];
__device__ __align__(1024) float g_hs[PB * PI];
__device__ __align__(1024) float g_hsp[4 * PB * PI];
__device__ __align__(1024) float g_E[(size_t)PM * PD];

// ---------------------------------------------------------------------------
// Helpers (baseline ISA only: cp.async + mma.sync + ldmatrix, all sm_80-)
// ---------------------------------------------------------------------------
__device__ __forceinline__ uint32_t smem_u32(const void* p) {
    uint32_t a;
    asm("{ .reg .u64 t; cvta.to.shared.u64 t, %1; cvt.u32.u64 %0, t; }" : "=r"(a) : "l"(p));
    return a;
}

#define CP_ASYNC16(dst, src) \
    asm volatile("cp.async.cg.shared.global [%0], [%1], 16;" :: "r"(dst), "l"(src))
#define CP_ASYNC_COMMIT() asm volatile("cp.async.commit_group;" ::: "memory")
#define CP_ASYNC_WAIT1() asm volatile("cp.async.wait_group 1;" ::: "memory")

__device__ __forceinline__ void ldsm_x4(uint32_t* r, uint32_t addr) {
    asm volatile(
        "ldmatrix.sync.aligned.m8n8.x4.shared.b16 {%0,%1,%2,%3}, [%4];"
        : "=r"(r[0]), "=r"(r[1]), "=r"(r[2]), "=r"(r[3]) : "r"(addr));
}

__device__ __forceinline__ void mma_bf16(float* c, const uint32_t* a, const uint32_t* b) {
    asm volatile(
        "mma.sync.aligned.m16n8k16.row.col.f32.bf16.bf16.f32 "
        "{%0,%1,%2,%3}, {%4,%5,%6,%7}, {%8,%9}, {%0,%1,%2,%3};"
        : "+f"(c[0]), "+f"(c[1]), "+f"(c[2]), "+f"(c[3])
        : "r"(a[0]), "r"(a[1]), "r"(a[2]), "r"(a[3]), "r"(b[0]), "r"(b[1]));
}

__device__ __forceinline__ void split2(float v, __nv_bfloat16& h, __nv_bfloat16& l) {
    h = __float2bfloat16(v);
    l = __float2bfloat16(v - __bfloat162float(h));
}

// ---------------------------------------------------------------------------
// Kernel: split fv -> bf16 hi/lo
// ---------------------------------------------------------------------------
__global__ __launch_bounds__(256) void split_fv_kernel(const float* __restrict__ in) {
    size_t i = (size_t)blockIdx.x * blockDim.x + threadIdx.x;   // float4 index
    const size_t n4 = (size_t)PM * PD / 4;
    if (i >= n4) return;
    float4 v = ((const float4*)in)[i];
    __nv_bfloat16 h0, h1, h2, h3, l0, l1, l2, l3;
    split2(v.x, h0, l0); split2(v.y, h1, l1);
    split2(v.z, h2, l2); split2(v.w, h3, l3);
    __nv_bfloat162* ph = (__nv_bfloat162*)g_fv_hi;
    __nv_bfloat162* pl = (__nv_bfloat162*)g_fv_lo;
    ph[2 * i]     = __nv_bfloat162(h0, h1);
    ph[2 * i + 1] = __nv_bfloat162(h2, h3);
    pl[2 * i]     = __nv_bfloat162(l0, l1);
    pl[2 * i + 1] = __nv_bfloat162(l2, l3);
}

// ---------------------------------------------------------------------------
// Kernel: transpose [R?,C] -> [C,R], split to bf16 hi/lo  (out stride = R)
// ---------------------------------------------------------------------------
__global__ void tsplit_kernel(const float* __restrict__ in,
                              __nv_bfloat16* __restrict__ hi,
                              __nv_bfloat16* __restrict__ lo,
                              int R, int C) {
    __shared__ float tile[32][33];
    int r0 = blockIdx.y * 32, c0 = blockIdx.x * 32;
    int tx = threadIdx.x, ty = threadIdx.y;   // (32, 8)
#pragma unroll
    for (int j = 0; j < 32; j += 8)
        tile[ty + j][tx] = in[(size_t)(r0 + ty + j) * C + c0 + tx];
    __syncthreads();
#pragma unroll
    for (int j = 0; j < 32; j += 8) {
        float v = tile[tx][ty + j];
        __nv_bfloat16 h, l;
        split2(v, h, l);
        size_t o = (size_t)(c0 + ty + j) * R + r0 + tx;
        hi[o] = h; lo[o] = l;
    }
}

// ---------------------------------------------------------------------------
// hs = hidden @ W_h + b_h   (k-split x4 for latency, then reduce)
// ---------------------------------------------------------------------------
__global__ __launch_bounds__(512) void hs_part_kernel(const float* __restrict__ hidden,
                                                      const float* __restrict__ Wh) {
    __shared__ float h[128];
    const int b = blockIdx.x;
    const int kc = blockIdx.y;
    const int i = threadIdx.x;
    if (i < 128) h[i] = hidden[b * PI + kc * 128 + i];
    __syncthreads();
    float s = 0.0f;
#pragma unroll 16
    for (int k = 0; k < 128; k++)
        s = fmaf(h[k], Wh[(size_t)(kc * 128 + k) * PI + i], s);
    g_hsp[((size_t)kc * PB + b) * PI + i] = s;
}

__global__ __launch_bounds__(512) void hs_reduce_kernel(const float* __restrict__ bh) {
    const int b = blockIdx.x;
    const int i = threadIdx.x;
    float s = bh[i];
#pragma unroll
    for (int kc = 0; kc < 4; kc++) s += g_hsp[((size_t)kc * PB + b) * PI + i];
    g_hs[b * PI + i] = s;
}

// ---------------------------------------------------------------------------
// mma.sync GEMM (bf16 3-MMA hi/lo split):  D[m,n] = sum_k A[m,k]*B[n,k]
// BM=BN=128, BK=32, 3-stage cp.async ring, 256 threads (8 warps, m64 x n32 each)
// Fragments via ldmatrix.x4 (stride 80B -> conflict-free).
// EPI1: out = D + b_f + hs[b]  -> split to g_T_hi/lo (bf16)
// else: out = D + b_a          -> g_E (fp32)
// ---------------------------------------------------------------------------
#define GK_BM 128
#define GK_BN 128
#define GK_BK 32
#define GK_RS 40                         // padded row stride (bf16 elements) = 80 bytes
#define GK_RSB 80
#define GK_TILE_B (GK_BM * GK_RSB)       // 10240 bytes
#define GK_STAGE_B (4 * GK_TILE_B)       // Ah, Al, Bh, Bl  = 40960
#define GK_STAGES 3
#define GEMM_SMEM (GK_STAGES * GK_STAGE_B)  // 122880

template<int NK, bool EPI1>
__global__ __launch_bounds__(256) void gemm_kernel(const float* __restrict__ bias) {
    constexpr int K = NK * GK_BK;
    extern __shared__ char smem[];
    const uint32_t sbase = smem_u32(smem);

    const int tid = threadIdx.x;
    const int wid = tid >> 5;
    const int lane = tid & 31;
    const int tq = lane >> 2;    // 0..7
    const int tp = lane & 3;     // 0..3
    const int warp_m = wid & 1;  // 2
    const int warp_n = wid >> 1; // 4
    const int m0 = warp_m * 64;
    const int n0 = warp_n * 32;

    // ldmatrix per-lane byte offsets within a tile
    // A (16x16 per mi): matrices {rows0-7 klo, rows8-15 klo, rows0-7 khi, rows8-15 khi}
    const uint32_t a_loff = (uint32_t)((lane & 15) * GK_RSB + ((lane >> 4) & 1) * 16);
    // B (two n8 frags per pair): {n0-7 klo, n0-7 khi, n8-15 klo, n8-15 khi}
    const uint32_t b_loff = (uint32_t)((((lane >> 4) & 1) * 8 + (lane & 7)) * GK_RSB +
                                       ((lane >> 3) & 1) * 16);

    const __nv_bfloat16* Agh = EPI1 ? g_fv_hi : g_T_hi;
    const __nv_bfloat16* Agl = EPI1 ? g_fv_lo : g_T_lo;
    const __nv_bfloat16* Bgh = EPI1 ? g_Wft_hi : g_Wat_hi;
    const __nv_bfloat16* Bgl = EPI1 ? g_Wft_lo : g_Wat_lo;

    const int rowBase = blockIdx.y * GK_BM;
    const int colBase = blockIdx.x * GK_BN;
    const __nv_bfloat16* A0h = Agh + (size_t)rowBase * K;
    const __nv_bfloat16* A0l = Agl + (size_t)rowBase * K;
    const __nv_bfloat16* B0h = Bgh + (size_t)colBase * K;
    const __nv_bfloat16* B0l = Bgl + (size_t)colBase * K;

    float acc[4][4][4];
#pragma unroll
    for (int mi = 0; mi < 4; mi++)
#pragma unroll
        for (int ni = 0; ni < 4; ni++)
#pragma unroll
            for (int e = 0; e < 4; e++) acc[mi][ni][e] = 0.0f;

    // load slots: 512 16B-chunks per tile (128 rows x 4), 2 per thread
    const int s0 = tid, s1 = tid + 256;
    const int r0_ = s0 >> 2, ch0 = s0 & 3;
    const int r1_ = s1 >> 2, ch1 = s1 & 3;
    const uint32_t so0 = (uint32_t)(r0_ * GK_RSB + ch0 * 16);
    const uint32_t so1 = (uint32_t)(r1_ * GK_RSB + ch1 * 16);

    auto load_stage = [&](int kt, int stg) {
        const uint32_t sb = sbase + stg * GK_STAGE_B;
        const int k0 = kt * GK_BK;
        {
            const size_t ga = (size_t)r0_ * K + k0 + ch0 * 8;
            CP_ASYNC16(sb + so0,                 A0h + ga);
            CP_ASYNC16(sb + GK_TILE_B + so0,     A0l + ga);
            CP_ASYNC16(sb + 2 * GK_TILE_B + so0, B0h + ga);
            CP_ASYNC16(sb + 3 * GK_TILE_B + so0, B0l + ga);
        }
        {
            const size_t ga = (size_t)r1_ * K + k0 + ch1 * 8;
            CP_ASYNC16(sb + so1,                 A0h + ga);
            CP_ASYNC16(sb + GK_TILE_B + so1,     A0l + ga);
            CP_ASYNC16(sb + 2 * GK_TILE_B + so1, B0h + ga);
            CP_ASYNC16(sb + 3 * GK_TILE_B + so1, B0l + ga);
        }
        CP_ASYNC_COMMIT();
    };

    // prologue: 2 stages in flight
    load_stage(0, 0);
    load_stage(1, 1);

    int stg_idx = 0;   // stage holding chunk kt
    for (int kt = 0; kt < NK; kt++) {
        CP_ASYNC_WAIT1();
        __syncthreads();

        if (kt + 2 < NK) {
            int free_stg = stg_idx + 2;
            if (free_stg >= GK_STAGES) free_stg -= GK_STAGES;
            load_stage(kt + 2, free_stg);
        } else {
            CP_ASYNC_COMMIT();   // empty group keeps wait_group accounting uniform
        }

        const uint32_t sb = sbase + (uint32_t)stg_idx * GK_STAGE_B;
        const uint32_t aBaseH = sb + (uint32_t)(m0 * GK_RSB) + a_loff;
        const uint32_t aBaseL = aBaseH + GK_TILE_B;
        const uint32_t bBaseH = sb + 2 * GK_TILE_B + (uint32_t)(n0 * GK_RSB) + b_loff;
        const uint32_t bBaseL = bBaseH + GK_TILE_B;

#pragma unroll
        for (int ks = 0; ks < 2; ks++) {
            const uint32_t ko = (uint32_t)(ks * 32);
            uint32_t ah[4][4], al[4][4], bh[2][4], bl[2][4];
#pragma unroll
            for (int mi = 0; mi < 4; mi++) {
                ldsm_x4(ah[mi], aBaseH + (uint32_t)(mi * 16 * GK_RSB) + ko);
                ldsm_x4(al[mi], aBaseL + (uint32_t)(mi * 16 * GK_RSB) + ko);
            }
#pragma unroll
            for (int p = 0; p < 2; p++) {
                ldsm_x4(bh[p], bBaseH + (uint32_t)(p * 16 * GK_RSB) + ko);
                ldsm_x4(bl[p], bBaseL + (uint32_t)(p * 16 * GK_RSB) + ko);
            }
#pragma unroll
            for (int mi = 0; mi < 4; mi++)
#pragma unroll
                for (int ni = 0; ni < 4; ni++) {
                    const uint32_t* bhf = &bh[ni >> 1][(ni & 1) * 2];
                    const uint32_t* blf = &bl[ni >> 1][(ni & 1) * 2];
                    mma_bf16(acc[mi][ni], ah[mi], bhf);
                    mma_bf16(acc[mi][ni], ah[mi], blf);
                    mma_bf16(acc[mi][ni], al[mi], bhf);
                }
        }
        __syncthreads();
        if (++stg_idx == GK_STAGES) stg_idx = 0;
    }

    // epilogue: c0,c1 at (row=tq, col=tp*2), c2,c3 at (row=tq+8)
#pragma unroll
    for (int mi = 0; mi < 4; mi++) {
        const int gr0 = rowBase + m0 + mi * 16 + tq;
        const int gr1 = gr0 + 8;
#pragma unroll
        for (int ni = 0; ni < 4; ni++) {
            const int gc = colBase + n0 + ni * 8 + tp * 2;
            float v0 = acc[mi][ni][0], v1 = acc[mi][ni][1];
            float v2 = acc[mi][ni][2], v3 = acc[mi][ni][3];
            const float b0 = bias[gc], b1 = bias[gc + 1];
            if (EPI1) {
                const int bb0 = gr0 / PL;
                const int bb1 = gr1 / PL;
                v0 += b0 + g_hs[bb0 * PI + gc];
                v1 += b1 + g_hs[bb0 * PI + gc + 1];
                v2 += b0 + g_hs[bb1 * PI + gc];
                v3 += b1 + g_hs[bb1 * PI + gc + 1];
                __nv_bfloat16 h0, h1, h2, h3, l0, l1, l2, l3;
                split2(v0, h0, l0); split2(v1, h1, l1);
                split2(v2, h2, l2); split2(v3, h3, l3);
                const size_t o0 = ((size_t)gr0 * PI + gc) >> 1;
                const size_t o1 = ((size_t)gr1 * PI + gc) >> 1;
                ((__nv_bfloat162*)g_T_hi)[o0] = __nv_bfloat162(h0, h1);
                ((__nv_bfloat162*)g_T_lo)[o0] = __nv_bfloat162(l0, l1);
                ((__nv_bfloat162*)g_T_hi)[o1] = __nv_bfloat162(h2, h3);
                ((__nv_bfloat162*)g_T_lo)[o1] = __nv_bfloat162(l2, l3);
            } else {
                float2 w0 = {v0 + b0, v1 + b1};
                float2 w1 = {v2 + b0, v3 + b1};
                *(float2*)(g_E + (size_t)gr0 * PD + gc) = w0;
                *(float2*)(g_E + (size_t)gr1 * PD + gc) = w1;
            }
        }
    }
}

// ---------------------------------------------------------------------------
// Softmax over L + alpha write + z reduce. Block per (b, 64-wide d-chunk).
// 224 threads = 28 row-groups x 8 col-groups; 7x8 elements per thread.
// ---------------------------------------------------------------------------
__global__ __launch_bounds__(224) void softmax_kernel(const float* __restrict__ fv,
                                                      float* __restrict__ z,
                                                      float* __restrict__ alpha) {
    __shared__ float red[28 * 64];
    __shared__ float colmax[64];
    __shared__ float colsum[64];

    const int tid = threadIdx.x;
    const int tc = tid & 7;
    const int tr = tid >> 3;
    const int b = blockIdx.y;
    const int dbase = blockIdx.x * 64;

    float acc[7][8];
#pragma unroll
    for (int r = 0; r < 7; r++) {
        const int l = tr * 7 + r;
        const size_t base = ((size_t)b * PL + l) * PD + dbase + tc * 8;
        float4 e0 = *(const float4*)(g_E + base);
        float4 e1 = *(const float4*)(g_E + base + 4);
        acc[r][0] = e0.x; acc[r][1] = e0.y; acc[r][2] = e0.z; acc[r][3] = e0.w;
        acc[r][4] = e1.x; acc[r][5] = e1.y; acc[r][6] = e1.z; acc[r][7] = e1.w;
    }

    float lm[8];
#pragma unroll
    for (int j = 0; j < 8; j++) {
        float m = acc[0][j];
#pragma unroll
        for (int r = 1; r < 7; r++) m = fmaxf(m, acc[r][j]);
        lm[j] = m;
    }
#pragma unroll
    for (int j = 0; j < 8; j++) red[tr * 64 + tc * 8 + j] = lm[j];
    __syncthreads();
    if (tid < 64) {
        float m = -CUDART_INF_F;
#pragma unroll
        for (int t = 0; t < 28; t++) m = fmaxf(m, red[t * 64 + tid]);
        colmax[tid] = m;
    }
    __syncthreads();
    float cm[8];
#pragma unroll
    for (int j = 0; j < 8; j++) cm[j] = colmax[tc * 8 + j];

    float ls[8];
#pragma unroll
    for (int j = 0; j < 8; j++) ls[j] = 0.0f;
#pragma unroll
    for (int r = 0; r < 7; r++)
#pragma unroll
        for (int j = 0; j < 8; j++) {
            float e = __expf(acc[r][j] - cm[j]);
            acc[r][j] = e;
            ls[j] += e;
        }
#pragma unroll
    for (int j = 0; j < 8; j++) red[tr * 64 + tc * 8 + j] = ls[j];
    __syncthreads();
    if (tid < 64) {
        float s = 0.0f;
#pragma unroll
        for (int t = 0; t < 28; t++) s += red[t * 64 + tid];
        colsum[tid] = s;
    }
    __syncthreads();
    float inv[8];
#pragma unroll
    for (int j = 0; j < 8; j++) inv[j] = 1.0f / colsum[tc * 8 + j];

    float zp[8];
#pragma unroll
    for (int j = 0; j < 8; j++) zp[j] = 0.0f;
#pragma unroll
    for (int r = 0; r < 7; r++) {
        const int l = tr * 7 + r;
        const size_t base = ((size_t)b * PL + l) * PD + dbase + tc * 8;
        float4 f0 = *(const float4*)(fv + base);
        float4 f1 = *(const float4*)(fv + base + 4);
        float a0 = acc[r][0] * inv[0], a1 = acc[r][1] * inv[1];
        float a2 = acc[r][2] * inv[2], a3 = acc[r][3] * inv[3];
        float a4 = acc[r][4] * inv[4], a5 = acc[r][5] * inv[5];
        float a6 = acc[r][6] * inv[6], a7 = acc[r][7] * inv[7];
        float4 o0 = {a0, a1, a2, a3};
        float4 o1 = {a4, a5, a6, a7};
        *(float4*)(alpha + base) = o0;
        *(float4*)(alpha + base + 4) = o1;
        zp[0] = fmaf(a0, f0.x, zp[0]); zp[1] = fmaf(a1, f0.y, zp[1]);
        zp[2] = fmaf(a2, f0.z, zp[2]); zp[3] = fmaf(a3, f0.w, zp[3]);
        zp[4] = fmaf(a4, f1.x, zp[4]); zp[5] = fmaf(a5, f1.y, zp[5]);
        zp[6] = fmaf(a6, f1.z, zp[6]); zp[7] = fmaf(a7, f1.w, zp[7]);
    }
#pragma unroll
    for (int j = 0; j < 8; j++) red[tr * 64 + tc * 8 + j] = zp[j];
    __syncthreads();
    if (tid < 64) {
        float s = 0.0f;
#pragma unroll
        for (int t = 0; t < 28; t++) s += red[t * 64 + tid];
        z[b * PD + dbase + tid] = s;
    }
}

// ---------------------------------------------------------------------------
// Launch
// ---------------------------------------------------------------------------
extern "C" void kernel_launch(void* const* d_in, const int* in_sizes, int n_in,
                              void* d_out, int out_size) {
    const float* fv     = (const float*)d_in[0];
    const float* hidden = (const float*)d_in[1];
    const float* W_f    = (const float*)d_in[2];
    const float* b_f    = (const float*)d_in[3];
    const float* W_h    = (const float*)d_in[4];
    const float* b_h    = (const float*)d_in[5];
    const float* W_a    = (const float*)d_in[6];
    const float* b_a    = (const float*)d_in[7];

    float* out   = (float*)d_out;
    float* z     = out;
    float* alpha = out + (size_t)PB * PD;

    cudaFuncSetAttribute(gemm_kernel<PD / GK_BK, true>,
                         cudaFuncAttributeMaxDynamicSharedMemorySize, GEMM_SMEM);
    cudaFuncSetAttribute(gemm_kernel<PI / GK_BK, false>,
                         cudaFuncAttributeMaxDynamicSharedMemorySize, GEMM_SMEM);

    __nv_bfloat16 *wft_hi, *wft_lo, *wat_hi, *wat_lo;
    cudaGetSymbolAddress((void**)&wft_hi, g_Wft_hi);
    cudaGetSymbolAddress((void**)&wft_lo, g_Wft_lo);
    cudaGetSymbolAddress((void**)&wat_hi, g_Wat_hi);
    cudaGetSymbolAddress((void**)&wat_lo, g_Wat_lo);

    // 1) conversions
    {
        size_t n4 = (size_t)PM * PD / 4;
        int blocks = (int)((n4 + 255) / 256);
        split_fv_kernel<<<blocks, 256>>>(fv);
    }
    tsplit_kernel<<<dim3(PI / 32, PD / 32), dim3(32, 8)>>>(W_f, wft_hi, wft_lo, PD, PI);
    tsplit_kernel<<<dim3(PD / 32, PI / 32), dim3(32, 8)>>>(W_a, wat_hi, wat_lo, PI, PD);

    // 2) hs (k-split + reduce)
    hs_part_kernel<<<dim3(PB, 4), 512>>>(hidden, W_h);
    hs_reduce_kernel<<<PB, PI>>>(b_h);

    // 3) GEMM1: T = fv @ W_f + b_f + hs   (M=12544, N=512, K=2048)
    gemm_kernel<PD / GK_BK, true>
        <<<dim3(PI / GK_BN, PM / GK_BM), 256, GEMM_SMEM>>>(b_f);

    // 4) GEMM2: E = T @ W_a + b_a         (M=12544, N=2048, K=512)
    gemm_kernel<PI / GK_BK, false>
        <<<dim3(PD / GK_BN, PM / GK_BM), 256, GEMM_SMEM>>>(b_a);

    // 5) softmax + alpha + z
    softmax_kernel<<<dim3(PD / 64, PB), 224>>>(fv, z, alpha);
}